// round 4
// baseline (speedup 1.0000x reference)
#include <cuda_runtime.h>
#include <cuda_bf16.h>
#include <cstdint>

#define T_ 100
#define GRID_P 132
// plane sizes in 32-bit words (each word = bf16x2, k-even in low half)
#define H_PL    65536      // 512x256
#define Z_PL    720896     // 512x2816
#define DT_T    16384      // per-t dt words
#define DT_PL   1638400    // 100*DT_T
#define WIH_PL  131072     // 1024x256 B-layout
#define W1H_PL  360448     // 2816x256
#define WEFF_PL 90112      // 2816x64
#define WC_PL   450560     // 320x2816

__device__ __align__(16) uint32_t g_h_pk[4*H_PL];     // [parity][plane hi/lo]
__device__ __align__(16) uint32_t g_nxt_pk[2*H_PL];   // [plane]
__device__ __align__(16) uint32_t g_z_pk[2*Z_PL];
__device__ __align__(16) uint32_t g_dt_pk[2*DT_PL];
__device__ __align__(16) uint32_t g_Wih_p[2*WIH_PL];
__device__ __align__(16) uint32_t g_Whh_p[2*WIH_PL];
__device__ __align__(16) uint32_t g_W1h_p[2*W1H_PL];
__device__ __align__(16) uint32_t g_Weff_p[2*WEFF_PL];
__device__ __align__(16) uint32_t g_Wc_p[2*WC_PL];
__device__ __align__(16) float g_c[512*256];
__device__ __align__(16) float g_part[4*512*320];
__device__ __align__(16) float g_bg[1024];
__device__ __align__(16) float g_cb[2816];
__device__ __align__(16) float g_bc[320];
__device__ unsigned g_cnt;
__device__ unsigned g_gen;

// ---------------- helpers ----------------
__device__ __forceinline__ float sigm(float x) { return 1.f / (1.f + __expf(-x)); }
__device__ __forceinline__ uint16_t b16c(float x){ __nv_bfloat16 b = __float2bfloat16(x); return *(uint16_t*)&b; }
__device__ __forceinline__ float b16f(uint16_t u){ __nv_bfloat16 b = *(__nv_bfloat16*)&u; return __bfloat162float(b); }
__device__ __forceinline__ void bsplit(float x, uint16_t& h, uint16_t& l){
    h = b16c(x); l = b16c(x - b16f(h));
}
__device__ __forceinline__ uint32_t pk2(uint16_t e0, uint16_t e1){ return (uint32_t)e0 | ((uint32_t)e1 << 16); }

__device__ __forceinline__ size_t awrd(int m, int k2, int K16){
    return ((size_t)((m >> 4) * K16 + (k2 >> 3))) * 128
         + ((((m & 7) << 2) | (k2 & 3)) << 2)
         + (((m >> 3) & 1) | (((k2 >> 2) & 1) << 1));
}
__device__ __forceinline__ size_t bwrd(int n, int k2, int K16){
    return ((size_t)((n >> 3) * K16 + (k2 >> 3))) * 64
         + ((((n & 7) << 2) | (k2 & 3)) << 1)
         + ((k2 >> 2) & 1);
}

__device__ __forceinline__ void mma16(float (&d)[4], const uint32_t (&a)[4], const uint32_t (&b)[2]){
    asm volatile(
        "mma.sync.aligned.m16n8k16.row.col.f32.bf16.bf16.f32 "
        "{%0,%1,%2,%3}, {%4,%5,%6,%7}, {%8,%9}, {%0,%1,%2,%3};\n"
        : "+f"(d[0]), "+f"(d[1]), "+f"(d[2]), "+f"(d[3])
        : "r"(a[0]), "r"(a[1]), "r"(a[2]), "r"(a[3]), "r"(b[0]), "r"(b[1]));
}

// grid-wide sense barrier (all GRID_P blocks co-resident)
__device__ __forceinline__ void gridbar(){
    __syncthreads();
    if (threadIdx.x == 0){
        unsigned gen = atomicAdd(&g_gen, 0u);
        __threadfence();
        if (atomicAdd(&g_cnt, 1u) == GRID_P - 1u){
            atomicExch(&g_cnt, 0u);
            __threadfence();
            atomicAdd(&g_gen, 1u);
        } else {
            while (atomicAdd(&g_gen, 0u) == gen) __nanosleep(64);
        }
        __threadfence();
    }
    __syncthreads();
}

// ---------------- pipelined bf16x3 GEMM segment ----------------
// 256 thr = 8 warps (wm 0..1, wn 0..3). BM=64. BN = 32*NT.
template<int NT>
__device__ __forceinline__ void gemm_bf16(
    const uint32_t* __restrict__ Ah, const uint32_t* __restrict__ Al,
    const uint32_t* __restrict__ Bh, const uint32_t* __restrict__ Bl,
    int K16A, int K16B, int ktbeg, int ktcnt,
    int mt0, int nt0, float (&acc)[2][NT][4], uint32_t* smem)
{
    const int tid = threadIdx.x, lane = tid & 31;
    const int wm = (tid >> 5) >> 2, wn = (tid >> 5) & 3;
    const int BW  = 256 * NT;        // B words per plane per stage
    const int STG = 1024 + 2 * BW;   // words per stage
    const int NCH = STG >> 2;        // 16B chunks per stage
    uint32_t sb = (uint32_t)__cvta_generic_to_shared(smem);

    auto issue = [&](int kt, int s){
        #pragma unroll
        for (int i = 0; i < NCH / 256; i++){
            int c = tid + i * 256;
            const uint32_t* src; uint32_t dst;
            if (c < 256){
                int pl = c >> 7, r = c & 127, mt = r >> 5, off = (r & 31) << 2;
                src = (pl ? Al : Ah) + ((size_t)(mt0 + mt) * K16A + kt) * 128 + off;
                dst = sb + (uint32_t)((s * STG + pl * 512 + mt * 128 + off) << 2);
            } else {
                int cb = c - 256;
                int pl = cb >= 64 * NT;
                int r  = pl ? cb - 64 * NT : cb;
                int nt = r >> 4, off = (r & 15) << 2;
                src = (pl ? Bl : Bh) + ((size_t)(nt0 + nt) * K16B + kt) * 64 + off;
                dst = sb + (uint32_t)((s * STG + 1024 + pl * BW + nt * 64 + off) << 2);
            }
            asm volatile("cp.async.cg.shared.global [%0], [%1], 16;\n" :: "r"(dst), "l"(src));
        }
        asm volatile("cp.async.commit_group;\n");
    };

    issue(ktbeg, 0);
    for (int i = 0; i < ktcnt; i++){
        if (i + 1 < ktcnt){ issue(ktbeg + i + 1, (i + 1) & 1); asm volatile("cp.async.wait_group 1;\n"); }
        else              { asm volatile("cp.async.wait_group 0;\n"); }
        __syncthreads();
        const uint32_t* sA = smem + (i & 1) * STG;
        const uint32_t* sB = sA + 1024;
        uint32_t ah[2][4], al[2][4];
        #pragma unroll
        for (int mt = 0; mt < 2; mt++){
            const uint32_t* p = sA + (wm * 2 + mt) * 128 + lane * 4;
            *(uint4*)ah[mt] = *(const uint4*)p;
            *(uint4*)al[mt] = *(const uint4*)(p + 512);
        }
        uint32_t bh[NT][2], bl[NT][2];
        #pragma unroll
        for (int nt = 0; nt < NT; nt++){
            const uint32_t* q = sB + (wn * NT + nt) * 64 + lane * 2;
            uint2 th = *(const uint2*)q;
            uint2 tl = *(const uint2*)(q + BW);
            bh[nt][0] = th.x; bh[nt][1] = th.y;
            bl[nt][0] = tl.x; bl[nt][1] = tl.y;
        }
        #pragma unroll
        for (int mt = 0; mt < 2; mt++)
        #pragma unroll
        for (int nt = 0; nt < NT; nt++){
            mma16(acc[mt][nt], ah[mt], bh[nt]);   // hi*hi
            mma16(acc[mt][nt], ah[mt], bl[nt]);   // hi*lo
            mma16(acc[mt][nt], al[mt], bh[nt]);   // lo*hi
        }
        __syncthreads();
    }
}

// ---------------- phase unit bodies ----------------
__device__ __forceinline__ void gates_unit(int mx, int ny, int par, uint32_t* sm)
{
    float acc[2][2][4] = {};
    const int mt0 = mx * 4, nt0 = ny * 8;
    gemm_bf16<2>(g_nxt_pk, g_nxt_pk + H_PL, g_Wih_p, g_Wih_p + WIH_PL, 16, 16, 0, 16, mt0, nt0, acc, sm);
    const uint32_t* hp = g_h_pk + (size_t)par * 2 * H_PL;
    gemm_bf16<2>(hp, hp + H_PL, g_Whh_p, g_Whh_p + WIH_PL, 16, 16, 0, 16, mt0, nt0, acc, sm);
    float* smf = (float*)sm;
    const int tid = threadIdx.x, lane = tid & 31;
    const int wm = (tid >> 5) >> 2, wn = (tid >> 5) & 3;
    #pragma unroll
    for (int mt = 0; mt < 2; mt++)
    #pragma unroll
    for (int nt = 0; nt < 2; nt++)
    #pragma unroll
    for (int r = 0; r < 4; r++){
        int rl = wm * 32 + mt * 16 + (lane >> 2) + ((r >> 1) << 3);
        int cl = wn * 16 + nt * 8 + ((lane & 3) << 1) + (r & 1);
        smf[rl * 64 + cl] = acc[mt][nt][r];
    }
    __syncthreads();
    const int m0 = mx * 64, n0 = ny * 64;
    uint32_t* hw = g_h_pk + (size_t)(par ^ 1) * 2 * H_PL;
    #pragma unroll
    for (int it = 0; it < 2; it++){
        int p = tid + it * 256;           // [0,512): 64 rows x 8 j-pairs
        int bl = p >> 3, jp = p & 7;
        float* gp = smf + bl * 64 + jp * 8;
        float4 ga = *(float4*)gp;
        float4 gb = *(float4*)(gp + 4);
        float4 ba = *(const float4*)&g_bg[n0 + jp * 8];
        float4 bb = *(const float4*)&g_bg[n0 + jp * 8 + 4];
        int b = m0 + bl;
        int j0 = (n0 >> 2) + jp * 2;
        float2 cc = *(float2*)&g_c[b * 256 + j0];
        float i0 = sigm(ga.x + ba.x), f0 = sigm(ga.y + ba.y);
        float g0 = tanhf(ga.z + ba.z), o0 = sigm(ga.w + ba.w);
        float i1 = sigm(gb.x + bb.x), f1 = sigm(gb.y + bb.y);
        float g1 = tanhf(gb.z + bb.z), o1 = sigm(gb.w + bb.w);
        float c0 = f0 * cc.x + i0 * g0, c1 = f1 * cc.y + i1 * g1;
        *(float2*)&g_c[b * 256 + j0] = make_float2(c0, c1);
        float h0 = o0 * tanhf(c0), h1 = o1 * tanhf(c1);
        uint16_t h0h, h0l, h1h, h1l;
        bsplit(h0, h0h, h0l); bsplit(h1, h1h, h1l);
        size_t w = awrd(b, j0 >> 1, 16);
        hw[w]        = pk2(h0h, h1h);
        hw[H_PL + w] = pk2(h0l, h1l);
    }
    __syncthreads();   // protect smf before next unit's cp.async
}

__device__ __forceinline__ void z_unit(int mx, int ny, int par, int t, uint32_t* sm)
{
    float acc[2][4][4] = {};
    const int mt0 = mx * 4, nt0 = ny * 16;
    const uint32_t* dt = g_dt_pk + (size_t)t * DT_T;
    gemm_bf16<4>(dt, dt + DT_PL, g_Weff_p, g_Weff_p + WEFF_PL, 4, 4, 0, 4, mt0, nt0, acc, sm);
    const uint32_t* hp = g_h_pk + (size_t)(par ^ 1) * 2 * H_PL;
    gemm_bf16<4>(hp, hp + H_PL, g_W1h_p, g_W1h_p + W1H_PL, 16, 16, 0, 16, mt0, nt0, acc, sm);
    const int tid = threadIdx.x, lane = tid & 31;
    const int wm = (tid >> 5) >> 2, wn = (tid >> 5) & 3;
    const int m0 = mx * 64, n0 = ny * 128;
    #pragma unroll
    for (int mt = 0; mt < 2; mt++){
        int r0 = m0 + wm * 32 + mt * 16 + (lane >> 2);
        #pragma unroll
        for (int nt = 0; nt < 4; nt++){
            int col = n0 + wn * 32 + nt * 8 + ((lane & 3) << 1);
            float2 cb2 = *(const float2*)&g_cb[col];
            int k2 = col >> 1;
            float v0 = fmaxf(acc[mt][nt][0] + cb2.x, 0.f);
            float v1 = fmaxf(acc[mt][nt][1] + cb2.y, 0.f);
            float v2 = fmaxf(acc[mt][nt][2] + cb2.x, 0.f);
            float v3 = fmaxf(acc[mt][nt][3] + cb2.y, 0.f);
            uint16_t h0, l0, h1, l1;
            bsplit(v0, h0, l0); bsplit(v1, h1, l1);
            size_t w = awrd(r0, k2, 176);
            g_z_pk[w] = pk2(h0, h1); g_z_pk[Z_PL + w] = pk2(l0, l1);
            bsplit(v2, h0, l0); bsplit(v3, h1, l1);
            w = awrd(r0 + 8, k2, 176);
            g_z_pk[w] = pk2(h0, h1); g_z_pk[Z_PL + w] = pk2(l0, l1);
        }
    }
}

__device__ __forceinline__ void nxt_unit(int mx, int ny, int s, uint32_t* sm)
{
    float acc[2][2][4] = {};
    const int mt0 = mx * 4, nt0 = ny * 8;
    gemm_bf16<2>(g_z_pk, g_z_pk + Z_PL, g_Wc_p, g_Wc_p + WC_PL, 176, 176, s * 44, 44, mt0, nt0, acc, sm);
    const int tid = threadIdx.x, lane = tid & 31;
    const int wm = (tid >> 5) >> 2, wn = (tid >> 5) & 3;
    const int m0 = mx * 64, n0 = ny * 64;
    float* pp = g_part + (size_t)s * 512 * 320;
    #pragma unroll
    for (int mt = 0; mt < 2; mt++)
    #pragma unroll
    for (int nt = 0; nt < 2; nt++){
        int row = m0 + wm * 32 + mt * 16 + (lane >> 2);
        int col = n0 + wn * 16 + nt * 8 + ((lane & 3) << 1);
        *(float2*)&pp[(size_t)row * 320 + col]       = make_float2(acc[mt][nt][0], acc[mt][nt][1]);
        *(float2*)&pp[(size_t)(row + 8) * 320 + col] = make_float2(acc[mt][nt][2], acc[mt][nt][3]);
    }
}

__device__ __forceinline__ void reduce_unit(int u, float* __restrict__ out, int t)
{
    int i = u * 256 + threadIdx.x;
    int b = i / 133, q = i - b * 133;
    if (q < 128){
        int n = q * 2;
        float v0 = g_bc[n], v1 = g_bc[n + 1];
        #pragma unroll
        for (int s = 0; s < 4; s++){
            const float* pp = &g_part[((size_t)s * 512 + b) * 320 + n];
            v0 += __ldcg(pp); v1 += __ldcg(pp + 1);
        }
        v0 = fmaxf(v0, 0.f); v1 = fmaxf(v1, 0.f);
        uint16_t h0, l0, h1, l1;
        bsplit(v0, h0, l0); bsplit(v1, h1, l1);
        size_t w = awrd(b, q, 16);
        g_nxt_pk[w]        = pk2(h0, h1);
        g_nxt_pk[H_PL + w] = pk2(l0, l1);
    } else {
        int p = q - 128;
        int n = 256 + p * 2;
        float v0 = g_bc[n], v1 = g_bc[n + 1];
        #pragma unroll
        for (int s = 0; s < 4; s++){
            const float* pp = &g_part[((size_t)s * 512 + b) * 320 + n];
            v0 += __ldcg(pp); v1 += __ldcg(pp + 1);
        }
        out[(size_t)b * 1000 + t * 10 + p * 2]     = 1.f / (1.f + __expf(-v0));
        out[(size_t)b * 1000 + t * 10 + p * 2 + 1] = 1.f / (1.f + __expf(-v1));
    }
}

// ---------------- persistent step kernel ----------------
__global__ __launch_bounds__(256, 1) void k_steps(float* __restrict__ out)
{
    __shared__ __align__(16) uint32_t sm[6144];
    const int bid = blockIdx.x;
    for (int t = 0; t < T_; t++){
        int par = t & 1;
        for (int u = bid; u < 128; u += GRID_P) gates_unit(u & 7, u >> 3, par, sm);
        gridbar();
        for (int u = bid; u < 176; u += GRID_P) z_unit(u & 7, u >> 3, par, t, sm);
        gridbar();
        for (int u = bid; u < 160; u += GRID_P) nxt_unit(u & 7, (u >> 3) % 5, u / 40, sm);
        gridbar();
        for (int u = bid; u < 266; u += GRID_P) reduce_unit(u, out, t);
        gridbar();
    }
}

// ---------------- one-time precompute ----------------
__global__ void k_pack_rnn(const float* __restrict__ Wih, const float* __restrict__ Whh,
                           const float* __restrict__ bih, const float* __restrict__ bhh)
{
    int idx = blockIdx.x * 256 + threadIdx.x;
    if (idx >= 1024 * 128) return;
    int p = idx >> 7, k2 = idx & 127;
    int j = p >> 2, g = p & 3;
    int row = g * 256 + j;
    size_t w = bwrd(p, k2, 16);
    uint16_t h0, l0, h1, l1;
    float a0 = Wih[(size_t)row * 256 + 2 * k2], a1 = Wih[(size_t)row * 256 + 2 * k2 + 1];
    bsplit(a0, h0, l0); bsplit(a1, h1, l1);
    g_Wih_p[w] = pk2(h0, h1); g_Wih_p[WIH_PL + w] = pk2(l0, l1);
    a0 = Whh[(size_t)row * 256 + 2 * k2]; a1 = Whh[(size_t)row * 256 + 2 * k2 + 1];
    bsplit(a0, h0, l0); bsplit(a1, h1, l1);
    g_Whh_p[w] = pk2(h0, h1); g_Whh_p[WIH_PL + w] = pk2(l0, l1);
    if (k2 == 0) g_bg[p] = bih[row] + bhh[row];
}

__global__ void k_pack_w1h(const float* __restrict__ W1)
{
    int idx = blockIdx.x * 256 + threadIdx.x;
    if (idx >= 2816 * 128) return;
    int n = idx >> 7, k2 = idx & 127;
    float a0 = W1[(size_t)n * 2816 + 2560 + 2 * k2];
    float a1 = W1[(size_t)n * 2816 + 2560 + 2 * k2 + 1];
    uint16_t h0, l0, h1, l1;
    bsplit(a0, h0, l0); bsplit(a1, h1, l1);
    size_t w = bwrd(n, k2, 16);
    g_W1h_p[w] = pk2(h0, h1); g_W1h_p[W1H_PL + w] = pk2(l0, l1);
}

// one block per output n; coalesced + block reduce
__global__ void k_cb(const float* __restrict__ W1, const float* __restrict__ b1,
                     const float* __restrict__ bd)
{
    __shared__ float red[256];
    int n = blockIdx.x;
    const float* w = W1 + (size_t)n * 2816;
    float s = 0.f;
    for (int i = threadIdx.x; i < 2560; i += 256) s += w[i] * bd[i & 255];
    red[threadIdx.x] = s; __syncthreads();
    for (int o = 128; o > 0; o >>= 1){
        if (threadIdx.x < o) red[threadIdx.x] += red[threadIdx.x + o];
        __syncthreads();
    }
    if (threadIdx.x == 0) g_cb[n] = b1[n] + red[0];
}

__global__ void k_weff(const float* __restrict__ W1, const float* __restrict__ Wd)
{
    __shared__ float sWd[1536];
    for (int i = threadIdx.x; i < 1536; i += 256) sWd[i] = Wd[i];
    __syncthreads();
    int idx = blockIdx.x * 256 + threadIdx.x;
    if (idx >= 2816 * 32) return;
    int n = idx >> 5, k2 = idx & 31;
    float v[2] = {0.f, 0.f};
    #pragma unroll
    for (int e = 0; e < 2; e++){
        int kk = 2 * k2 + e;
        if (kk < 60){
            int nd = kk / 6, d = kk - nd * 6;
            const float* w = W1 + (size_t)n * 2816 + nd * 256;
            float s = 0.f;
            #pragma unroll 8
            for (int i = 0; i < 256; i++) s += w[i] * sWd[i * 6 + d];
            v[e] = s;
        }
    }
    uint16_t h0, l0, h1, l1;
    bsplit(v[0], h0, l0); bsplit(v[1], h1, l1);
    size_t w = bwrd(n, k2, 4);
    g_Weff_p[w] = pk2(h0, h1); g_Weff_p[WEFF_PL + w] = pk2(l0, l1);
}

__global__ void k_pack_wc(const float* __restrict__ W2, const float* __restrict__ Wv,
                          const float* __restrict__ b2, const float* __restrict__ bv)
{
    int idx = blockIdx.x * 256 + threadIdx.x;
    if (idx >= 320 * 1408) return;
    int n = idx / 1408, k2 = idx - n * 1408;
    int k = 2 * k2;
    float a0 = 0.f, a1 = 0.f;
    if (n < 256){ a0 = W2[(size_t)n * 2816 + k]; a1 = W2[(size_t)n * 2816 + k + 1]; }
    else if (n < 266){ a0 = Wv[(size_t)(n - 256) * 2816 + k]; a1 = Wv[(size_t)(n - 256) * 2816 + k + 1]; }
    uint16_t h0, l0, h1, l1;
    bsplit(a0, h0, l0); bsplit(a1, h1, l1);
    size_t w = bwrd(n, k2, 176);
    g_Wc_p[w] = pk2(h0, h1); g_Wc_p[WC_PL + w] = pk2(l0, l1);
    if (k2 == 0) g_bc[n] = (n < 256) ? b2[n] : ((n < 266) ? bv[n - 256] : 0.f);
}

__global__ void k_pack_dt(const float* __restrict__ desc)
{
    int idx = blockIdx.x * 256 + threadIdx.x;
    if (idx >= 100 * 512 * 32) return;
    int t = idx / 16384, r = idx - t * 16384;
    int b = r >> 5, k2 = r & 31;
    int kk = 2 * k2;
    float a0 = (kk < 60)     ? desc[((size_t)b * 100 + t) * 60 + kk]     : 0.f;
    float a1 = (kk + 1 < 60) ? desc[((size_t)b * 100 + t) * 60 + kk + 1] : 0.f;
    uint16_t h0, l0, h1, l1;
    bsplit(a0, h0, l0); bsplit(a1, h1, l1);
    size_t w = (size_t)t * DT_T + awrd(b, k2, 4);
    g_dt_pk[w] = pk2(h0, h1); g_dt_pk[DT_PL + w] = pk2(l0, l1);
}

__global__ void k_init()
{
    int i = blockIdx.x * 256 + threadIdx.x;
    if (i == 0){ g_cnt = 0u; g_gen = 0u; }
    if (i < 2 * H_PL)            g_h_pk[i] = 0u;               // parity 0, both planes
    else if (i < 4 * H_PL)       g_nxt_pk[i - 2 * H_PL] = 0u;
    else if (i < 4 * H_PL + 512 * 256) g_c[i - 4 * H_PL] = 0.f;
}

// ---------------- launch ----------------
extern "C" void kernel_launch(void* const* d_in, const int* in_sizes, int n_in,
                              void* d_out, int out_size)
{
    const float* desc = (const float*)d_in[0];
    const float* Wd   = (const float*)d_in[1];
    const float* bd   = (const float*)d_in[2];
    const float* W1   = (const float*)d_in[3];
    const float* b1   = (const float*)d_in[4];
    const float* W2   = (const float*)d_in[5];
    const float* b2   = (const float*)d_in[6];
    const float* Wv   = (const float*)d_in[7];
    const float* bv   = (const float*)d_in[8];
    const float* Wih  = (const float*)d_in[9];
    const float* Whh  = (const float*)d_in[10];
    const float* bih  = (const float*)d_in[11];
    const float* bhh  = (const float*)d_in[12];
    float* out = (float*)d_out;

    k_pack_rnn<<<512,  256>>>(Wih, Whh, bih, bhh);
    k_pack_w1h<<<1408, 256>>>(W1);
    k_cb      <<<2816, 256>>>(W1, b1, bd);
    k_weff    <<<352,  256>>>(W1, Wd);
    k_pack_wc <<<1760, 256>>>(W2, Wv, b2, bv);
    k_pack_dt <<<6400, 256>>>(desc);
    k_init    <<<1536, 256>>>();

    k_steps<<<GRID_P, 256>>>(out);
}

// round 13
// speedup vs baseline: 1.4930x; 1.4930x over previous
#include <cuda_runtime.h>
#include <cuda_bf16.h>
#include <cstdint>

#define T_ 100
// plane sizes in 32-bit words (each word = bf16x2, k-even in low half)
#define H_PL    65536      // 512x256
#define Z_PL    720896     // 512x2816
#define DT_T    16384      // per-t dt words
#define DT_PL   1638400    // 100*DT_T
#define WIH_PL  131072     // 1024x256 B-layout
#define W1H_PL  360448     // 2816x256
#define WEFF_PL 90112      // 2816x64
#define WC_PL   540672     // 384x2816: 48*176*64

__device__ __align__(16) uint32_t g_h_pk[4*H_PL];     // [parity][plane hi/lo]
__device__ __align__(16) uint32_t g_nxt_pk[2*H_PL];   // [plane]
__device__ __align__(16) uint32_t g_z_pk[2*Z_PL];
__device__ __align__(16) uint32_t g_dt_pk[2*DT_PL];
__device__ __align__(16) uint32_t g_Wih_p[2*WIH_PL];
__device__ __align__(16) uint32_t g_Whh_p[2*WIH_PL];
__device__ __align__(16) uint32_t g_W1h_p[2*W1H_PL];
__device__ __align__(16) uint32_t g_Weff_p[2*WEFF_PL];
__device__ __align__(16) uint32_t g_Wc_p[2*WC_PL];
__device__ __align__(16) float g_c[512*256];
__device__ __align__(16) float g_part[11*512*384];
__device__ __align__(16) float g_bg[1024];
__device__ __align__(16) float g_cb[2816];
__device__ __align__(16) float g_bc[384];

// ---------------- helpers ----------------
__device__ __forceinline__ float sigm(float x) { return 1.f / (1.f + __expf(-x)); }
__device__ __forceinline__ uint16_t b16c(float x){ __nv_bfloat16 b = __float2bfloat16(x); return *(uint16_t*)&b; }
__device__ __forceinline__ float b16f(uint16_t u){ __nv_bfloat16 b = *(__nv_bfloat16*)&u; return __bfloat162float(b); }
__device__ __forceinline__ void bsplit(float x, uint16_t& h, uint16_t& l){
    h = b16c(x); l = b16c(x - b16f(h));
}
__device__ __forceinline__ uint32_t pk2(uint16_t e0, uint16_t e1){ return (uint32_t)e0 | ((uint32_t)e1 << 16); }

__device__ __forceinline__ size_t awrd(int m, int k2, int K16){
    return ((size_t)((m >> 4) * K16 + (k2 >> 3))) * 128
         + ((((m & 7) << 2) | (k2 & 3)) << 2)
         + (((m >> 3) & 1) | (((k2 >> 2) & 1) << 1));
}
__device__ __forceinline__ size_t bwrd(int n, int k2, int K16){
    return ((size_t)((n >> 3) * K16 + (k2 >> 3))) * 64
         + ((((n & 7) << 2) | (k2 & 3)) << 1)
         + ((k2 >> 2) & 1);
}

__device__ __forceinline__ void mma16(float (&d)[4], const uint32_t (&a)[4], const uint32_t (&b)[2]){
    asm volatile(
        "mma.sync.aligned.m16n8k16.row.col.f32.bf16.bf16.f32 "
        "{%0,%1,%2,%3}, {%4,%5,%6,%7}, {%8,%9}, {%0,%1,%2,%3};\n"
        : "+f"(d[0]), "+f"(d[1]), "+f"(d[2]), "+f"(d[3])
        : "r"(a[0]), "r"(a[1]), "r"(a[2]), "r"(a[3]), "r"(b[0]), "r"(b[1]));
}

// ---------------- NS-stage pipelined bf16x3 GEMM segment ----------------
// 256 thr = 8 warps (wm 0..1, wn 0..3). BM=64. BN = 32*NT.
// Ring of NS stages, issue depth NS-1, ONE __syncthreads per k-iter:
//   wait(group i) -> sync -> issue(i+NS-1) -> compute(i)
// Safe: each warp's compute(i-1) precedes its iter-i sync in program order,
// so the sync guarantees stage (i+NS-1)%NS (last computed at iter i-1 when
// NS=2, or i+NS-1-NS = i-1) is free before any warp overwrites it.
template<int NT, int NS>
__device__ __forceinline__ void gemm_bf16(
    const uint32_t* __restrict__ Ah, const uint32_t* __restrict__ Al,
    const uint32_t* __restrict__ Bh, const uint32_t* __restrict__ Bl,
    int K16A, int K16B, int ktbeg, int ktcnt,
    int mt0, int nt0, float (&acc)[2][NT][4], uint32_t* smem)
{
    const int tid = threadIdx.x, lane = tid & 31;
    const int wm = (tid >> 5) >> 2, wn = (tid >> 5) & 3;
    const int BW  = 256 * NT;        // B words per plane per stage
    const int STG = 1024 + 2 * BW;   // words per stage
    const int NCH = STG >> 2;        // 16B chunks per stage
    uint32_t sb = (uint32_t)__cvta_generic_to_shared(smem);

    __syncthreads();   // prior smem users (previous call / epilogue) done

    auto issue = [&](int kt, int s){
        #pragma unroll
        for (int i = 0; i < NCH / 256; i++){
            int c = tid + i * 256;
            const uint32_t* src; uint32_t dst;
            if (c < 256){
                int pl = c >> 7, r = c & 127, mt = r >> 5, off = (r & 31) << 2;
                src = (pl ? Al : Ah) + ((size_t)(mt0 + mt) * K16A + kt) * 128 + off;
                dst = sb + (uint32_t)((s * STG + pl * 512 + mt * 128 + off) << 2);
            } else {
                int cb = c - 256;
                int pl = cb >= 64 * NT;
                int r  = pl ? cb - 64 * NT : cb;
                int nt = r >> 4, off = (r & 15) << 2;
                src = (pl ? Bl : Bh) + ((size_t)(nt0 + nt) * K16B + kt) * 64 + off;
                dst = sb + (uint32_t)((s * STG + 1024 + pl * BW + nt * 64 + off) << 2);
            }
            asm volatile("cp.async.cg.shared.global [%0], [%1], 16;\n" :: "r"(dst), "l"(src));
        }
        asm volatile("cp.async.commit_group;\n");
    };

    // prologue: fill NS-1 stages
    #pragma unroll
    for (int p = 0; p < NS - 1; p++)
        if (p < ktcnt) issue(ktbeg + p, p);

    int s = 0;
    for (int i = 0; i < ktcnt; i++){
        if (i + 1 < ktcnt && NS > 2) asm volatile("cp.async.wait_group %0;\n" :: "n"(NS - 2));
        else if (i + 1 < ktcnt)      asm volatile("cp.async.wait_group 0;\n");
        else                         asm volatile("cp.async.wait_group 0;\n");
        __syncthreads();
        if (i + NS - 1 < ktcnt){
            int s2 = s + NS - 1; if (s2 >= NS) s2 -= NS;
            issue(ktbeg + i + NS - 1, s2);
        }
        const uint32_t* sA = smem + s * STG;
        const uint32_t* sB = sA + 1024;
        uint32_t ah[2][4], al[2][4];
        #pragma unroll
        for (int mt = 0; mt < 2; mt++){
            const uint32_t* p = sA + (wm * 2 + mt) * 128 + lane * 4;
            *(uint4*)ah[mt] = *(const uint4*)p;
            *(uint4*)al[mt] = *(const uint4*)(p + 512);
        }
        uint32_t bh[NT][2], bl[NT][2];
        #pragma unroll
        for (int nt = 0; nt < NT; nt++){
            const uint32_t* q = sB + (wn * NT + nt) * 64 + lane * 2;
            uint2 th = *(const uint2*)q;
            uint2 tl = *(const uint2*)(q + BW);
            bh[nt][0] = th.x; bh[nt][1] = th.y;
            bl[nt][0] = tl.x; bl[nt][1] = tl.y;
        }
        #pragma unroll
        for (int mt = 0; mt < 2; mt++)
        #pragma unroll
        for (int nt = 0; nt < NT; nt++){
            mma16(acc[mt][nt], ah[mt], bh[nt]);   // hi*hi
            mma16(acc[mt][nt], ah[mt], bl[nt]);   // hi*lo
            mma16(acc[mt][nt], al[mt], bh[nt]);   // lo*hi
        }
        s++; if (s >= NS) s = 0;
    }
}

// ---------------- per-step kernels ----------------

// gates = nxt@Wih^T + h@Whh^T (+bias), fused LSTM pointwise, writes h packed
// NT=2, NS=3: 3*2048 words = 24KB static smem
__global__ __launch_bounds__(256) void k_gates_lstm(int par)
{
    __shared__ __align__(16) uint32_t sm[6144];
    float acc[2][2][4] = {};
    const int mt0 = blockIdx.x * 4, nt0 = blockIdx.y * 8;
    gemm_bf16<2,3>(g_nxt_pk, g_nxt_pk + H_PL, g_Wih_p, g_Wih_p + WIH_PL, 16, 16, 0, 16, mt0, nt0, acc, sm);
    const uint32_t* hp = g_h_pk + (size_t)par * 2 * H_PL;
    gemm_bf16<2,3>(hp, hp + H_PL, g_Whh_p, g_Whh_p + WIH_PL, 16, 16, 0, 16, mt0, nt0, acc, sm);
    __syncthreads();   // all warps done with stage smem
    float* smf = (float*)sm;
    const int tid = threadIdx.x, lane = tid & 31;
    const int wm = (tid >> 5) >> 2, wn = (tid >> 5) & 3;
    #pragma unroll
    for (int mt = 0; mt < 2; mt++)
    #pragma unroll
    for (int nt = 0; nt < 2; nt++)
    #pragma unroll
    for (int r = 0; r < 4; r++){
        int rl = wm * 32 + mt * 16 + (lane >> 2) + ((r >> 1) << 3);
        int cl = wn * 16 + nt * 8 + ((lane & 3) << 1) + (r & 1);
        smf[rl * 64 + cl] = acc[mt][nt][r];
    }
    __syncthreads();
    const int m0 = blockIdx.x * 64, n0 = blockIdx.y * 64;
    uint32_t* hw = g_h_pk + (size_t)(par ^ 1) * 2 * H_PL;
    #pragma unroll
    for (int it = 0; it < 2; it++){
        int p = tid + it * 256;           // [0,512): 64 rows x 8 j-pairs
        int bl = p >> 3, jp = p & 7;
        float* gp = smf + bl * 64 + jp * 8;
        float4 ga = *(float4*)gp;
        float4 gb = *(float4*)(gp + 4);
        float4 ba = *(const float4*)&g_bg[n0 + jp * 8];
        float4 bb = *(const float4*)&g_bg[n0 + jp * 8 + 4];
        int b = m0 + bl;
        int j0 = (n0 >> 2) + jp * 2;
        float2 cc = *(float2*)&g_c[b * 256 + j0];
        float i0 = sigm(ga.x + ba.x), f0 = sigm(ga.y + ba.y);
        float g0 = tanhf(ga.z + ba.z), o0 = sigm(ga.w + ba.w);
        float i1 = sigm(gb.x + bb.x), f1 = sigm(gb.y + bb.y);
        float g1 = tanhf(gb.z + bb.z), o1 = sigm(gb.w + bb.w);
        float c0 = f0 * cc.x + i0 * g0, c1 = f1 * cc.y + i1 * g1;
        *(float2*)&g_c[b * 256 + j0] = make_float2(c0, c1);
        float h0 = o0 * tanhf(c0), h1 = o1 * tanhf(c1);
        uint16_t h0h, h0l, h1h, h1l;
        bsplit(h0, h0h, h0l); bsplit(h1, h1h, h1l);
        size_t w = awrd(b, j0 >> 1, 16);
        hw[w]        = pk2(h0h, h1h);
        hw[H_PL + w] = pk2(h0l, h1l);
    }
}

// z = relu(dt@Weff^T + h@W1h^T + cb), BN=256 (NT=8), NS=2: 2*5120 = 40KB static
__global__ __launch_bounds__(256) void k_z(int par, int t)
{
    __shared__ __align__(16) uint32_t sm[10240];
    float acc[2][8][4] = {};
    const int mt0 = blockIdx.x * 4, nt0 = blockIdx.y * 32;
    const uint32_t* dt = g_dt_pk + (size_t)t * DT_T;
    gemm_bf16<8,2>(dt, dt + DT_PL, g_Weff_p, g_Weff_p + WEFF_PL, 4, 4, 0, 4, mt0, nt0, acc, sm);
    const uint32_t* hp = g_h_pk + (size_t)(par ^ 1) * 2 * H_PL;
    gemm_bf16<8,2>(hp, hp + H_PL, g_W1h_p, g_W1h_p + W1H_PL, 16, 16, 0, 16, mt0, nt0, acc, sm);
    const int tid = threadIdx.x, lane = tid & 31;
    const int wm = (tid >> 5) >> 2, wn = (tid >> 5) & 3;
    const int m0 = blockIdx.x * 64, n0 = blockIdx.y * 256;
    #pragma unroll
    for (int mt = 0; mt < 2; mt++){
        int r0 = m0 + wm * 32 + mt * 16 + (lane >> 2);
        #pragma unroll
        for (int nt = 0; nt < 8; nt++){
            int col = n0 + wn * 64 + nt * 8 + ((lane & 3) << 1);
            float2 cb2 = *(const float2*)&g_cb[col];
            int k2 = col >> 1;
            float v0 = fmaxf(acc[mt][nt][0] + cb2.x, 0.f);
            float v1 = fmaxf(acc[mt][nt][1] + cb2.y, 0.f);
            float v2 = fmaxf(acc[mt][nt][2] + cb2.x, 0.f);
            float v3 = fmaxf(acc[mt][nt][3] + cb2.y, 0.f);
            uint16_t h0, l0, h1, l1;
            bsplit(v0, h0, l0); bsplit(v1, h1, l1);
            size_t w = awrd(r0, k2, 176);
            g_z_pk[w] = pk2(h0, h1); g_z_pk[Z_PL + w] = pk2(l0, l1);
            bsplit(v2, h0, l0); bsplit(v3, h1, l1);
            w = awrd(r0 + 8, k2, 176);
            g_z_pk[w] = pk2(h0, h1); g_z_pk[Z_PL + w] = pk2(l0, l1);
        }
    }
}

// split-K(11) partials of z @ [W2;Wv;pad]^T, BN=128 (NT=4), NS=3: 36KB static
__global__ __launch_bounds__(256) void k_nxt()
{
    __shared__ __align__(16) uint32_t sm[9216];
    float acc[2][4][4] = {};
    const int mt0 = blockIdx.x * 4, nt0 = blockIdx.y * 16, s = blockIdx.z;
    gemm_bf16<4,3>(g_z_pk, g_z_pk + Z_PL, g_Wc_p, g_Wc_p + WC_PL, 176, 176, s * 16, 16, mt0, nt0, acc, sm);
    const int tid = threadIdx.x, lane = tid & 31;
    const int wm = (tid >> 5) >> 2, wn = (tid >> 5) & 3;
    const int m0 = blockIdx.x * 64, n0 = blockIdx.y * 128;
    float* pp = g_part + (size_t)s * 512 * 384;
    #pragma unroll
    for (int mt = 0; mt < 2; mt++)
    #pragma unroll
    for (int nt = 0; nt < 4; nt++){
        int row = m0 + wm * 32 + mt * 16 + (lane >> 2);
        int col = n0 + wn * 32 + nt * 8 + ((lane & 3) << 1);
        *(float2*)&pp[(size_t)row * 384 + col]       = make_float2(acc[mt][nt][0], acc[mt][nt][1]);
        *(float2*)&pp[(size_t)(row + 8) * 384 + col] = make_float2(acc[mt][nt][2], acc[mt][nt][3]);
    }
}

// deterministic reduce + activations; writes packed nxt and output attention
__global__ void k_reduce(float* __restrict__ out, int t)
{
    int i = blockIdx.x * 256 + threadIdx.x;
    if (i >= 512 * 133) return;
    int b = i / 133, q = i - b * 133;
    int n = 2 * q;
    float v0 = g_bc[n], v1 = g_bc[n + 1];
    #pragma unroll
    for (int s = 0; s < 11; s++){
        const float* pp = &g_part[((size_t)s * 512 + b) * 384 + n];
        v0 += __ldcg(pp); v1 += __ldcg(pp + 1);
    }
    if (n < 256){
        v0 = fmaxf(v0, 0.f); v1 = fmaxf(v1, 0.f);
        uint16_t h0, l0, h1, l1;
        bsplit(v0, h0, l0); bsplit(v1, h1, l1);
        size_t w = awrd(b, q, 16);
        g_nxt_pk[w]        = pk2(h0, h1);
        g_nxt_pk[H_PL + w] = pk2(l0, l1);
    } else {
        out[(size_t)b * 1000 + t * 10 + (n - 256)]     = 1.f / (1.f + __expf(-v0));
        out[(size_t)b * 1000 + t * 10 + (n - 256) + 1] = 1.f / (1.f + __expf(-v1));
    }
}

// ---------------- one-time precompute ----------------
__global__ void k_pack_rnn(const float* __restrict__ Wih, const float* __restrict__ Whh,
                           const float* __restrict__ bih, const float* __restrict__ bhh)
{
    int idx = blockIdx.x * 256 + threadIdx.x;
    if (idx >= 1024 * 128) return;
    int p = idx >> 7, k2 = idx & 127;
    int j = p >> 2, g = p & 3;
    int row = g * 256 + j;
    size_t w = bwrd(p, k2, 16);
    uint16_t h0, l0, h1, l1;
    float a0 = Wih[(size_t)row * 256 + 2 * k2], a1 = Wih[(size_t)row * 256 + 2 * k2 + 1];
    bsplit(a0, h0, l0); bsplit(a1, h1, l1);
    g_Wih_p[w] = pk2(h0, h1); g_Wih_p[WIH_PL + w] = pk2(l0, l1);
    a0 = Whh[(size_t)row * 256 + 2 * k2]; a1 = Whh[(size_t)row * 256 + 2 * k2 + 1];
    bsplit(a0, h0, l0); bsplit(a1, h1, l1);
    g_Whh_p[w] = pk2(h0, h1); g_Whh_p[WIH_PL + w] = pk2(l0, l1);
    if (k2 == 0) g_bg[p] = bih[row] + bhh[row];
}

__global__ void k_pack_w1h(const float* __restrict__ W1)
{
    int idx = blockIdx.x * 256 + threadIdx.x;
    if (idx >= 2816 * 128) return;
    int n = idx >> 7, k2 = idx & 127;
    float a0 = W1[(size_t)n * 2816 + 2560 + 2 * k2];
    float a1 = W1[(size_t)n * 2816 + 2560 + 2 * k2 + 1];
    uint16_t h0, l0, h1, l1;
    bsplit(a0, h0, l0); bsplit(a1, h1, l1);
    size_t w = bwrd(n, k2, 16);
    g_W1h_p[w] = pk2(h0, h1); g_W1h_p[W1H_PL + w] = pk2(l0, l1);
}

// one block per output n; coalesced + block reduce
__global__ void k_cb(const float* __restrict__ W1, const float* __restrict__ b1,
                     const float* __restrict__ bd)
{
    __shared__ float red[256];
    int n = blockIdx.x;
    const float* w = W1 + (size_t)n * 2816;
    float s = 0.f;
    for (int i = threadIdx.x; i < 2560; i += 256) s += w[i] * bd[i & 255];
    red[threadIdx.x] = s; __syncthreads();
    for (int o = 128; o > 0; o >>= 1){
        if (threadIdx.x < o) red[threadIdx.x] += red[threadIdx.x + o];
        __syncthreads();
    }
    if (threadIdx.x == 0) g_cb[n] = b1[n] + red[0];
}

__global__ void k_weff(const float* __restrict__ W1, const float* __restrict__ Wd)
{
    __shared__ float sWd[1536];
    for (int i = threadIdx.x; i < 1536; i += 256) sWd[i] = Wd[i];
    __syncthreads();
    int idx = blockIdx.x * 256 + threadIdx.x;
    if (idx >= 2816 * 32) return;
    int n = idx >> 5, k2 = idx & 31;
    float v[2] = {0.f, 0.f};
    #pragma unroll
    for (int e = 0; e < 2; e++){
        int kk = 2 * k2 + e;
        if (kk < 60){
            int nd = kk / 6, d = kk - nd * 6;
            const float* w = W1 + (size_t)n * 2816 + nd * 256;
            float s = 0.f;
            #pragma unroll 8
            for (int i = 0; i < 256; i++) s += w[i] * sWd[i * 6 + d];
            v[e] = s;
        }
    }
    uint16_t h0, l0, h1, l1;
    bsplit(v[0], h0, l0); bsplit(v[1], h1, l1);
    size_t w = bwrd(n, k2, 4);
    g_Weff_p[w] = pk2(h0, h1); g_Weff_p[WEFF_PL + w] = pk2(l0, l1);
}

__global__ void k_pack_wc(const float* __restrict__ W2, const float* __restrict__ Wv,
                          const float* __restrict__ b2, const float* __restrict__ bv)
{
    int idx = blockIdx.x * 256 + threadIdx.x;
    if (idx >= 384 * 1408) return;
    int n = idx / 1408, k2 = idx - n * 1408;
    int k = 2 * k2;
    float a0 = 0.f, a1 = 0.f;
    if (n < 256){ a0 = W2[(size_t)n * 2816 + k]; a1 = W2[(size_t)n * 2816 + k + 1]; }
    else if (n < 266){ a0 = Wv[(size_t)(n - 256) * 2816 + k]; a1 = Wv[(size_t)(n - 256) * 2816 + k + 1]; }
    uint16_t h0, l0, h1, l1;
    bsplit(a0, h0, l0); bsplit(a1, h1, l1);
    size_t w = bwrd(n, k2, 176);
    g_Wc_p[w] = pk2(h0, h1); g_Wc_p[WC_PL + w] = pk2(l0, l1);
    if (k2 == 0) g_bc[n] = (n < 256) ? b2[n] : ((n < 266) ? bv[n - 256] : 0.f);
}

__global__ void k_pack_dt(const float* __restrict__ desc)
{
    int idx = blockIdx.x * 256 + threadIdx.x;
    if (idx >= 100 * 512 * 32) return;
    int t = idx / 16384, r = idx - t * 16384;
    int b = r >> 5, k2 = r & 31;
    int kk = 2 * k2;
    float a0 = (kk < 60)     ? desc[((size_t)b * 100 + t) * 60 + kk]     : 0.f;
    float a1 = (kk + 1 < 60) ? desc[((size_t)b * 100 + t) * 60 + kk + 1] : 0.f;
    uint16_t h0, l0, h1, l1;
    bsplit(a0, h0, l0); bsplit(a1, h1, l1);
    size_t w = (size_t)t * DT_T + awrd(b, k2, 4);
    g_dt_pk[w] = pk2(h0, h1); g_dt_pk[DT_PL + w] = pk2(l0, l1);
}

__global__ void k_init()
{
    int i = blockIdx.x * 256 + threadIdx.x;
    if (i < 2 * H_PL)            g_h_pk[i] = 0u;               // parity 0, both planes
    else if (i < 4 * H_PL)       g_nxt_pk[i - 2 * H_PL] = 0u;
    else if (i < 4 * H_PL + 512 * 256) g_c[i - 4 * H_PL] = 0.f;
}

// ---------------- launch ----------------
extern "C" void kernel_launch(void* const* d_in, const int* in_sizes, int n_in,
                              void* d_out, int out_size)
{
    const float* desc = (const float*)d_in[0];
    const float* Wd   = (const float*)d_in[1];
    const float* bd   = (const float*)d_in[2];
    const float* W1   = (const float*)d_in[3];
    const float* b1   = (const float*)d_in[4];
    const float* W2   = (const float*)d_in[5];
    const float* b2   = (const float*)d_in[6];
    const float* Wv   = (const float*)d_in[7];
    const float* bv   = (const float*)d_in[8];
    const float* Wih  = (const float*)d_in[9];
    const float* Whh  = (const float*)d_in[10];
    const float* bih  = (const float*)d_in[11];
    const float* bhh  = (const float*)d_in[12];
    float* out = (float*)d_out;

    k_pack_rnn<<<512,  256>>>(Wih, Whh, bih, bhh);
    k_pack_w1h<<<1408, 256>>>(W1);
    k_cb      <<<2816, 256>>>(W1, b1, bd);
    k_weff    <<<352,  256>>>(W1, Wd);
    k_pack_wc <<<2112, 256>>>(W2, Wv, b2, bv);
    k_pack_dt <<<6400, 256>>>(desc);
    k_init    <<<1536, 256>>>();

    for (int t = 0; t < T_; t++) {
        int par = t & 1;
        k_gates_lstm<<<dim3(8, 16),     256>>>(par);
        k_z         <<<dim3(8, 11),     256>>>(par, t);
        k_nxt       <<<dim3(8, 3, 11),  256>>>();
        k_reduce    <<<266, 256>>>(out, t);
    }
}

// round 14
// speedup vs baseline: 2.3142x; 1.5501x over previous
#include <cuda_runtime.h>
#include <cuda_fp16.h>
#include <cstdint>

#define T_ 100
// plane sizes in 32-bit words (each word = fp16x2, k-even in low half)
#define H_PL    65536      // 512x256
#define Z_PL    720896     // 512x2816
#define DT_T    16384      // per-t dt words
#define DT_PL   1638400    // 100*DT_T
#define WIH_PL  131072     // 1024x256 B-layout
#define W1H_PL  360448     // 2816x256
#define WEFF_PL 90112      // 2816x64
#define WC_PL   540672     // 384x2816: 48*176*64

__device__ __align__(16) uint32_t g_h_pk[2*H_PL];     // [parity]
__device__ __align__(16) uint32_t g_nxt_pk[H_PL];
__device__ __align__(16) uint32_t g_z_pk[Z_PL];
__device__ __align__(16) uint32_t g_dt_pk[DT_PL];
__device__ __align__(16) uint32_t g_Wih_p[WIH_PL];
__device__ __align__(16) uint32_t g_Whh_p[WIH_PL];
__device__ __align__(16) uint32_t g_W1h_p[W1H_PL];
__device__ __align__(16) uint32_t g_Weff_p[WEFF_PL];
__device__ __align__(16) uint32_t g_Wc_p[WC_PL];
__device__ __align__(16) float g_c[512*256];
__device__ __align__(16) float g_part[11*512*384];
__device__ __align__(16) float g_bg[1024];
__device__ __align__(16) float g_cb[2816];
__device__ __align__(16) float g_bc[384];

// ---------------- helpers ----------------
__device__ __forceinline__ float sigm(float x) { return 1.f / (1.f + __expf(-x)); }
__device__ __forceinline__ uint16_t h16(float x){ __half h = __float2half_rn(x); return *(uint16_t*)&h; }
__device__ __forceinline__ uint32_t pk2(uint16_t e0, uint16_t e1){ return (uint32_t)e0 | ((uint32_t)e1 << 16); }

__device__ __forceinline__ size_t awrd(int m, int k2, int K16){
    return ((size_t)((m >> 4) * K16 + (k2 >> 3))) * 128
         + ((((m & 7) << 2) | (k2 & 3)) << 2)
         + (((m >> 3) & 1) | (((k2 >> 2) & 1) << 1));
}
__device__ __forceinline__ size_t bwrd(int n, int k2, int K16){
    return ((size_t)((n >> 3) * K16 + (k2 >> 3))) * 64
         + ((((n & 7) << 2) | (k2 & 3)) << 1)
         + ((k2 >> 2) & 1);
}

__device__ __forceinline__ void mma16f(float (&d)[4], const uint32_t (&a)[4], const uint32_t (&b)[2]){
    asm volatile(
        "mma.sync.aligned.m16n8k16.row.col.f32.f16.f16.f32 "
        "{%0,%1,%2,%3}, {%4,%5,%6,%7}, {%8,%9}, {%0,%1,%2,%3};\n"
        : "+f"(d[0]), "+f"(d[1]), "+f"(d[2]), "+f"(d[3])
        : "r"(a[0]), "r"(a[1]), "r"(a[2]), "r"(a[3]), "r"(b[0]), "r"(b[1]));
}

// ---------------- NS-stage pipelined fp16 GEMM segment ----------------
// 256 thr = 8 warps (wm 0..1, wn 0..3). BM=64. BN = 32*NT. Single plane.
// Ring of NS stages, issue depth NS-1, ONE __syncthreads per k-iter:
//   wait(allow NS-2 in flight) -> sync -> issue(i+NS-1) -> compute(i)
template<int NT, int NS>
__device__ __forceinline__ void gemm_fp16(
    const uint32_t* __restrict__ Ah, const uint32_t* __restrict__ Bh,
    int K16A, int K16B, int ktbeg, int ktcnt,
    int mt0, int nt0, float (&acc)[2][NT][4], uint32_t* smem)
{
    const int tid = threadIdx.x, lane = tid & 31;
    const int wm = (tid >> 5) >> 2, wn = (tid >> 5) & 3;
    const int STG = 512 + 256 * NT;  // words per stage (A 512 + B 256*NT)
    const int NCH = STG >> 2;        // 16B chunks per stage
    uint32_t sb = (uint32_t)__cvta_generic_to_shared(smem);

    __syncthreads();   // prior smem users (previous call / epilogue) done

    auto issue = [&](int kt, int s){
        #pragma unroll
        for (int i = 0; i < (NCH + 255) / 256; i++){
            int c = tid + i * 256;
            if (c < NCH){
                const uint32_t* src; uint32_t dst;
                if (c < 128){
                    int mt = c >> 5, off = (c & 31) << 2;
                    src = Ah + ((size_t)(mt0 + mt) * K16A + kt) * 128 + off;
                    dst = sb + (uint32_t)((s * STG + mt * 128 + off) << 2);
                } else {
                    int r = c - 128;
                    int nt = r >> 4, off = (r & 15) << 2;
                    src = Bh + ((size_t)(nt0 + nt) * K16B + kt) * 64 + off;
                    dst = sb + (uint32_t)((s * STG + 512 + nt * 64 + off) << 2);
                }
                asm volatile("cp.async.cg.shared.global [%0], [%1], 16;\n" :: "r"(dst), "l"(src));
            }
        }
        asm volatile("cp.async.commit_group;\n");
    };

    // prologue: fill NS-1 stages
    #pragma unroll
    for (int p = 0; p < NS - 1; p++)
        if (p < ktcnt) issue(ktbeg + p, p);

    int s = 0;
    for (int i = 0; i < ktcnt; i++){
        if (i + 1 < ktcnt && NS > 2) asm volatile("cp.async.wait_group %0;\n" :: "n"(NS - 2));
        else                         asm volatile("cp.async.wait_group 0;\n");
        __syncthreads();
        if (i + NS - 1 < ktcnt){
            int s2 = s + NS - 1; if (s2 >= NS) s2 -= NS;
            issue(ktbeg + i + NS - 1, s2);
        }
        const uint32_t* sA = smem + s * STG;
        const uint32_t* sB = sA + 512;
        uint32_t a[2][4];
        #pragma unroll
        for (int mt = 0; mt < 2; mt++)
            *(uint4*)a[mt] = *(const uint4*)(sA + (wm * 2 + mt) * 128 + lane * 4);
        uint32_t bf[NT][2];
        #pragma unroll
        for (int nt = 0; nt < NT; nt++){
            uint2 tv = *(const uint2*)(sB + (wn * NT + nt) * 64 + lane * 2);
            bf[nt][0] = tv.x; bf[nt][1] = tv.y;
        }
        #pragma unroll
        for (int mt = 0; mt < 2; mt++)
        #pragma unroll
        for (int nt = 0; nt < NT; nt++)
            mma16f(acc[mt][nt], a[mt], bf[nt]);
        s++; if (s >= NS) s = 0;
    }
}

// ---------------- per-step kernels ----------------

// gates = nxt@Wih^T + h@Whh^T (+bias), fused LSTM pointwise, writes h packed
// NT=2, NS=4: 4*1024 words = 16KB smem (reused as 64x64 f32 epilogue buffer)
__global__ __launch_bounds__(256) void k_gates_lstm(int par)
{
    __shared__ __align__(16) uint32_t sm[4096];
    float acc[2][2][4] = {};
    const int mt0 = blockIdx.x * 4, nt0 = blockIdx.y * 8;
    gemm_fp16<2,4>(g_nxt_pk, g_Wih_p, 16, 16, 0, 16, mt0, nt0, acc, sm);
    const uint32_t* hp = g_h_pk + (size_t)par * H_PL;
    gemm_fp16<2,4>(hp, g_Whh_p, 16, 16, 0, 16, mt0, nt0, acc, sm);
    __syncthreads();   // all warps done with stage smem
    float* smf = (float*)sm;
    const int tid = threadIdx.x, lane = tid & 31;
    const int wm = (tid >> 5) >> 2, wn = (tid >> 5) & 3;
    #pragma unroll
    for (int mt = 0; mt < 2; mt++)
    #pragma unroll
    for (int nt = 0; nt < 2; nt++)
    #pragma unroll
    for (int r = 0; r < 4; r++){
        int rl = wm * 32 + mt * 16 + (lane >> 2) + ((r >> 1) << 3);
        int cl = wn * 16 + nt * 8 + ((lane & 3) << 1) + (r & 1);
        smf[rl * 64 + cl] = acc[mt][nt][r];
    }
    __syncthreads();
    const int m0 = blockIdx.x * 64, n0 = blockIdx.y * 64;
    uint32_t* hw = g_h_pk + (size_t)(par ^ 1) * H_PL;
    #pragma unroll
    for (int it = 0; it < 2; it++){
        int p = tid + it * 256;           // [0,512): 64 rows x 8 j-pairs
        int bl = p >> 3, jp = p & 7;
        float* gp = smf + bl * 64 + jp * 8;
        float4 ga = *(float4*)gp;
        float4 gb = *(float4*)(gp + 4);
        float4 ba = *(const float4*)&g_bg[n0 + jp * 8];
        float4 bb = *(const float4*)&g_bg[n0 + jp * 8 + 4];
        int b = m0 + bl;
        int j0 = (n0 >> 2) + jp * 2;
        float2 cc = *(float2*)&g_c[b * 256 + j0];
        float i0 = sigm(ga.x + ba.x), f0 = sigm(ga.y + ba.y);
        float g0 = tanhf(ga.z + ba.z), o0 = sigm(ga.w + ba.w);
        float i1 = sigm(gb.x + bb.x), f1 = sigm(gb.y + bb.y);
        float g1 = tanhf(gb.z + bb.z), o1 = sigm(gb.w + bb.w);
        float c0 = f0 * cc.x + i0 * g0, c1 = f1 * cc.y + i1 * g1;
        *(float2*)&g_c[b * 256 + j0] = make_float2(c0, c1);
        float h0 = o0 * tanhf(c0), h1 = o1 * tanhf(c1);
        size_t w = awrd(b, j0 >> 1, 16);
        hw[w] = pk2(h16(h0), h16(h1));
    }
}

// z = relu(dt@Weff^T + h@W1h^T + cb), BN=256 (NT=8), NS=3: 3*2560 words = 30KB
__global__ __launch_bounds__(256) void k_z(int par, int t)
{
    __shared__ __align__(16) uint32_t sm[7680];
    float acc[2][8][4] = {};
    const int mt0 = blockIdx.x * 4, nt0 = blockIdx.y * 32;
    const uint32_t* dt = g_dt_pk + (size_t)t * DT_T;
    gemm_fp16<8,3>(dt, g_Weff_p, 4, 4, 0, 4, mt0, nt0, acc, sm);
    const uint32_t* hp = g_h_pk + (size_t)(par ^ 1) * H_PL;
    gemm_fp16<8,3>(hp, g_W1h_p, 16, 16, 0, 16, mt0, nt0, acc, sm);
    const int tid = threadIdx.x, lane = tid & 31;
    const int wm = (tid >> 5) >> 2, wn = (tid >> 5) & 3;
    const int m0 = blockIdx.x * 64, n0 = blockIdx.y * 256;
    #pragma unroll
    for (int mt = 0; mt < 2; mt++){
        int r0 = m0 + wm * 32 + mt * 16 + (lane >> 2);
        #pragma unroll
        for (int nt = 0; nt < 8; nt++){
            int col = n0 + wn * 64 + nt * 8 + ((lane & 3) << 1);
            float2 cb2 = *(const float2*)&g_cb[col];
            int k2 = col >> 1;
            float v0 = fmaxf(acc[mt][nt][0] + cb2.x, 0.f);
            float v1 = fmaxf(acc[mt][nt][1] + cb2.y, 0.f);
            float v2 = fmaxf(acc[mt][nt][2] + cb2.x, 0.f);
            float v3 = fmaxf(acc[mt][nt][3] + cb2.y, 0.f);
            g_z_pk[awrd(r0, k2, 176)]     = pk2(h16(v0), h16(v1));
            g_z_pk[awrd(r0 + 8, k2, 176)] = pk2(h16(v2), h16(v3));
        }
    }
}

// split-K(11) partials of z @ [W2;Wv;pad]^T, BN=128 (NT=4), NS=3: 18KB
__global__ __launch_bounds__(256) void k_nxt()
{
    __shared__ __align__(16) uint32_t sm[4608];
    float acc[2][4][4] = {};
    const int mt0 = blockIdx.x * 4, nt0 = blockIdx.y * 16, s = blockIdx.z;
    gemm_fp16<4,3>(g_z_pk, g_Wc_p, 176, 176, s * 16, 16, mt0, nt0, acc, sm);
    const int tid = threadIdx.x, lane = tid & 31;
    const int wm = (tid >> 5) >> 2, wn = (tid >> 5) & 3;
    const int m0 = blockIdx.x * 64, n0 = blockIdx.y * 128;
    float* pp = g_part + (size_t)s * 512 * 384;
    #pragma unroll
    for (int mt = 0; mt < 2; mt++)
    #pragma unroll
    for (int nt = 0; nt < 4; nt++){
        int row = m0 + wm * 32 + mt * 16 + (lane >> 2);
        int col = n0 + wn * 32 + nt * 8 + ((lane & 3) << 1);
        *(float2*)&pp[(size_t)row * 384 + col]       = make_float2(acc[mt][nt][0], acc[mt][nt][1]);
        *(float2*)&pp[(size_t)(row + 8) * 384 + col] = make_float2(acc[mt][nt][2], acc[mt][nt][3]);
    }
}

// deterministic reduce + activations; writes packed nxt and output attention
__global__ void k_reduce(float* __restrict__ out, int t)
{
    int i = blockIdx.x * 256 + threadIdx.x;
    if (i >= 512 * 133) return;
    int b = i / 133, q = i - b * 133;
    int n = 2 * q;
    float v0 = g_bc[n], v1 = g_bc[n + 1];
    #pragma unroll
    for (int s = 0; s < 11; s++){
        const float* pp = &g_part[((size_t)s * 512 + b) * 384 + n];
        v0 += __ldcg(pp); v1 += __ldcg(pp + 1);
    }
    if (n < 256){
        v0 = fmaxf(v0, 0.f); v1 = fmaxf(v1, 0.f);
        g_nxt_pk[awrd(b, q, 16)] = pk2(h16(v0), h16(v1));
    } else {
        out[(size_t)b * 1000 + t * 10 + (n - 256)]     = 1.f / (1.f + __expf(-v0));
        out[(size_t)b * 1000 + t * 10 + (n - 256) + 1] = 1.f / (1.f + __expf(-v1));
    }
}

// ---------------- one-time precompute ----------------
__global__ void k_pack_rnn(const float* __restrict__ Wih, const float* __restrict__ Whh,
                           const float* __restrict__ bih, const float* __restrict__ bhh)
{
    int idx = blockIdx.x * 256 + threadIdx.x;
    if (idx >= 1024 * 128) return;
    int p = idx >> 7, k2 = idx & 127;
    int j = p >> 2, g = p & 3;
    int row = g * 256 + j;
    size_t w = bwrd(p, k2, 16);
    g_Wih_p[w] = pk2(h16(Wih[(size_t)row * 256 + 2 * k2]), h16(Wih[(size_t)row * 256 + 2 * k2 + 1]));
    g_Whh_p[w] = pk2(h16(Whh[(size_t)row * 256 + 2 * k2]), h16(Whh[(size_t)row * 256 + 2 * k2 + 1]));
    if (k2 == 0) g_bg[p] = bih[row] + bhh[row];
}

__global__ void k_pack_w1h(const float* __restrict__ W1)
{
    int idx = blockIdx.x * 256 + threadIdx.x;
    if (idx >= 2816 * 128) return;
    int n = idx >> 7, k2 = idx & 127;
    g_W1h_p[bwrd(n, k2, 16)] = pk2(h16(W1[(size_t)n * 2816 + 2560 + 2 * k2]),
                                   h16(W1[(size_t)n * 2816 + 2560 + 2 * k2 + 1]));
}

// fused: cb reduction + Weff projection, one W1-row pass per block
__global__ void k_weff_cb(const float* __restrict__ W1, const float* __restrict__ b1,
                          const float* __restrict__ bd, const float* __restrict__ Wd)
{
    __shared__ float w1r[2560];
    __shared__ float sWd[1536];
    __shared__ float red[256];
    __shared__ float wef[256];
    __shared__ float sW[64];
    int n = blockIdx.x, tid = threadIdx.x;
    const float* src = W1 + (size_t)n * 2816;
    for (int i = tid; i < 2560; i += 256) w1r[i] = src[i];
    for (int i = tid; i < 1536; i += 256) sWd[i] = Wd[i];
    __syncthreads();
    float s = 0.f;
    for (int i = tid; i < 2560; i += 256) s += w1r[i] * bd[i & 255];
    red[tid] = s; __syncthreads();
    for (int o = 128; o > 0; o >>= 1){
        if (tid < o) red[tid] += red[tid + o];
        __syncthreads();
    }
    if (tid == 0) g_cb[n] = b1[n] + red[0];
    // Weff: 64 outputs x 4 i-slices
    int kk = tid & 63, sl = tid >> 6;
    float v = 0.f;
    if (kk < 60){
        int nd = kk / 6, d = kk - nd * 6;
        const float* wr = w1r + nd * 256;
        #pragma unroll 8
        for (int i = sl * 64; i < sl * 64 + 64; i++) v += wr[i] * sWd[i * 6 + d];
    }
    wef[tid] = v; __syncthreads();
    if (tid < 64) sW[tid] = wef[tid] + wef[tid + 64] + wef[tid + 128] + wef[tid + 192];
    __syncthreads();
    if (tid < 32)
        g_Weff_p[bwrd(n, tid, 4)] = pk2(h16(sW[2 * tid]), h16(sW[2 * tid + 1]));
}

__global__ void k_pack_wc(const float* __restrict__ W2, const float* __restrict__ Wv,
                          const float* __restrict__ b2, const float* __restrict__ bv)
{
    int idx = blockIdx.x * 256 + threadIdx.x;
    if (idx >= 384 * 1408) return;
    int n = idx / 1408, k2 = idx - n * 1408;
    int k = 2 * k2;
    float a0 = 0.f, a1 = 0.f;
    if (n < 256){ a0 = W2[(size_t)n * 2816 + k]; a1 = W2[(size_t)n * 2816 + k + 1]; }
    else if (n < 266){ a0 = Wv[(size_t)(n - 256) * 2816 + k]; a1 = Wv[(size_t)(n - 256) * 2816 + k + 1]; }
    g_Wc_p[bwrd(n, k2, 176)] = pk2(h16(a0), h16(a1));
    if (k2 == 0) g_bc[n] = (n < 256) ? b2[n] : ((n < 266) ? bv[n - 256] : 0.f);
}

__global__ void k_pack_dt(const float* __restrict__ desc)
{
    int idx = blockIdx.x * 256 + threadIdx.x;
    if (idx >= 100 * 512 * 32) return;
    int t = idx / 16384, r = idx - t * 16384;
    int b = r >> 5, k2 = r & 31;
    int kk = 2 * k2;
    float a0 = (kk < 60)     ? desc[((size_t)b * 100 + t) * 60 + kk]     : 0.f;
    float a1 = (kk + 1 < 60) ? desc[((size_t)b * 100 + t) * 60 + kk + 1] : 0.f;
    g_dt_pk[(size_t)t * DT_T + awrd(b, k2, 4)] = pk2(h16(a0), h16(a1));
}

__global__ void k_init()
{
    int i = blockIdx.x * 256 + threadIdx.x;
    if (i < H_PL)                 g_h_pk[i] = 0u;               // parity 0
    else if (i < 2 * H_PL)        g_nxt_pk[i - H_PL] = 0u;
    else if (i < 2 * H_PL + 512 * 256) g_c[i - 2 * H_PL] = 0.f;
}

// ---------------- launch ----------------
extern "C" void kernel_launch(void* const* d_in, const int* in_sizes, int n_in,
                              void* d_out, int out_size)
{
    const float* desc = (const float*)d_in[0];
    const float* Wd   = (const float*)d_in[1];
    const float* bd   = (const float*)d_in[2];
    const float* W1   = (const float*)d_in[3];
    const float* b1   = (const float*)d_in[4];
    const float* W2   = (const float*)d_in[5];
    const float* b2   = (const float*)d_in[6];
    const float* Wv   = (const float*)d_in[7];
    const float* bv   = (const float*)d_in[8];
    const float* Wih  = (const float*)d_in[9];
    const float* Whh  = (const float*)d_in[10];
    const float* bih  = (const float*)d_in[11];
    const float* bhh  = (const float*)d_in[12];
    float* out = (float*)d_out;

    k_pack_rnn<<<512,  256>>>(Wih, Whh, bih, bhh);
    k_pack_w1h<<<1408, 256>>>(W1);
    k_weff_cb <<<2816, 256>>>(W1, b1, bd, Wd);
    k_pack_wc <<<2112, 256>>>(W2, Wv, b2, bv);
    k_pack_dt <<<6400, 256>>>(desc);
    k_init    <<<768,  256>>>();

    for (int t = 0; t < T_; t++) {
        int par = t & 1;
        k_gates_lstm<<<dim3(8, 16),     256>>>(par);
        k_z         <<<dim3(8, 11),     256>>>(par, t);
        k_nxt       <<<dim3(8, 3, 11),  256>>>();
        k_reduce    <<<266, 256>>>(out, t);
    }
}